// round 4
// baseline (speedup 1.0000x reference)
#include <cuda_runtime.h>
#include <cuda_fp16.h>
#include <cstdint>
#include <cstddef>

// Problem dims
#define L_DIM 1024
#define B_DIM 32
#define D_DIM 1024
#define M_DIM (L_DIM * B_DIM)     // 32768 rows (l*B+b)
#define N_DIM 3072                // 3*D output cols (planar-permuted)
#define KA    1024                // A storage: x fp16
#define NKT   16                  // K = 1024 = 16 tiles of 64
#define P_DIM (B_DIM * D_DIM)     // 32768 lanes
#define NC    16                  // scan chunks
#define LC    64                  // steps per chunk

// ---------------- device scratch (static: no allocs allowed) ----------------
__device__ __half g_A[(size_t)M_DIM * KA];            // 64 MB: x fp16, (M, 1024)
__device__ __half g_Bm[(size_t)N_DIM * D_DIM];        // 6 MB: permuted W^T fp16
__device__ __half g_u0h[(size_t)M_DIM * D_DIM];       // 64 MB (fp16 u0)
__device__ __half g_g1[(size_t)M_DIM * D_DIM];        // 64 MB (post-sigmoid fp16)
__device__ __half g_g2[(size_t)M_DIM * D_DIM];        // 64 MB (post-sigmoid fp16)
__device__ float  g_cA[(size_t)NC * P_DIM];           // chunk A
__device__ float  g_cB[(size_t)NC * P_DIM];           // chunk B
__device__ float  g_cS[(size_t)NC * P_DIM];           // chunk start c

// ---------------- ptx helpers ----------------
__device__ __forceinline__ uint32_t smem_u32(const void* p) {
    uint32_t a;
    asm("{ .reg .u64 t; cvta.to.shared.u64 t, %1; cvt.u32.u64 %0, t; }" : "=r"(a) : "l"(p));
    return a;
}
__device__ __forceinline__ void cp16(uint32_t dst, const void* src) {
    asm volatile("cp.async.cg.shared.global [%0], [%1], 16;" :: "r"(dst), "l"(src));
}
__device__ __forceinline__ void cp_commit() { asm volatile("cp.async.commit_group;"); }
__device__ __forceinline__ void cp_wait2()  { asm volatile("cp.async.wait_group 2;"); }
__device__ __forceinline__ void cp_wait1()  { asm volatile("cp.async.wait_group 1;"); }
__device__ __forceinline__ void cp_wait0()  { asm volatile("cp.async.wait_group 0;"); }

__device__ __forceinline__ void ldsm4(uint32_t* r, uint32_t addr) {
    asm volatile("ldmatrix.sync.aligned.m8n8.x4.shared.b16 {%0,%1,%2,%3}, [%4];"
                 : "=r"(r[0]), "=r"(r[1]), "=r"(r[2]), "=r"(r[3]) : "r"(addr));
}
__device__ __forceinline__ void mma16816(float* d, const uint32_t* a, const uint32_t* b) {
    asm volatile(
        "mma.sync.aligned.m16n8k16.row.col.f32.f16.f16.f32 "
        "{%0,%1,%2,%3}, {%4,%5,%6,%7}, {%8,%9}, {%0,%1,%2,%3};"
        : "+f"(d[0]), "+f"(d[1]), "+f"(d[2]), "+f"(d[3])
        : "r"(a[0]), "r"(a[1]), "r"(a[2]), "r"(a[3]), "r"(b[0]), "r"(b[1]));
}

// ---------------- conversion kernels ----------------
__global__ void conv_x_kernel(const float* __restrict__ x) {
    int idx = blockIdx.x * blockDim.x + threadIdx.x;
    float4 v = *(const float4*)(x + (size_t)idx * 4);
    *(__half2*)(g_A + (size_t)idx * 4)     = __floats2half2_rn(v.x, v.y);
    *(__half2*)(g_A + (size_t)idx * 4 + 2) = __floats2half2_rn(v.z, v.w);
}

// W (D, 3D) interleaved -> planar-permuted transposed fp16: g_Bm[n][k]
__global__ void conv_w_kernel(const float* __restrict__ W) {
    int idx = blockIdx.x * blockDim.x + threadIdx.x;      // < 3072*1024
    int n = idx >> 10, k = idx & 1023;
    int seg = n >> 10, d = n & 1023;
    g_Bm[(size_t)n * D_DIM + k] = __float2half_rn(W[(size_t)k * N_DIM + 3 * d + seg]);
}

// ---------------- GEMM: 128(M) x 256(N), 256 threads, warp tile 64x64, 4 stages ----------------
#define TILE_M 128
#define TILE_N 256
#define STAGE_BYTES (TILE_M * 128 + TILE_N * 128)   // 48KB
#define NSTAGE 4
#define SMEM_BYTES  (NSTAGE * STAGE_BYTES)          // 192KB

__device__ __forceinline__ void load_tile(uint32_t sb, int t, int stage, int bm, int bn, int tid) {
    int koff = t * 64;
    uint32_t sA = sb + stage * STAGE_BYTES;
    uint32_t sB = sA + TILE_M * 128;
    const __half* Ag = g_A  + (size_t)(bm * TILE_M) * KA + koff;
    const __half* Bg = g_Bm + (size_t)(bn * TILE_N) * D_DIM + koff;
    #pragma unroll
    for (int it = 0; it < 12; ++it) {
        int i = tid + it * 256;                  // 0..3071
        if (i < 1024) {
            int row = i >> 3, j = i & 7;
            cp16(sA + row * 128 + ((j ^ (row & 7)) << 4),
                 Ag + (size_t)row * KA + j * 8);
        } else {
            int li = i - 1024;
            int row = li >> 3, j = li & 7;
            cp16(sB + row * 128 + ((j ^ (row & 7)) << 4),
                 Bg + (size_t)row * D_DIM + j * 8);
        }
    }
}

__global__ void __launch_bounds__(256, 1)
gemm_kernel(const float* __restrict__ bias) {
    extern __shared__ __align__(1024) char smem[];
    uint32_t sb = smem_u32(smem);
    int tid = threadIdx.x, wid = tid >> 5, lane = tid & 31;
    int bn = blockIdx.x, bm = blockIdx.y;
    int warp_m = (wid >> 2) * 64;     // 0,64
    int warp_n = (wid & 3) * 64;      // 0,64,128,192

    float acc[4][8][4];
    #pragma unroll
    for (int mi = 0; mi < 4; ++mi)
        #pragma unroll
        for (int ni = 0; ni < 8; ++ni)
            #pragma unroll
            for (int j = 0; j < 4; ++j) acc[mi][ni][j] = 0.0f;

    int rowA = warp_m + (lane & 15);
    int kgrpA = lane >> 4;
    int nBrow = warp_n + ((lane >> 4) << 3) + (lane & 7);
    int kgrpB = (lane >> 3) & 1;

    load_tile(sb, 0, 0, bm, bn, tid); cp_commit();
    load_tile(sb, 1, 1, bm, bn, tid); cp_commit();
    load_tile(sb, 2, 2, bm, bn, tid); cp_commit();

    for (int t = 0; t < NKT; ++t) {
        if (t < NKT - 2) cp_wait2();
        else if (t == NKT - 2) cp_wait1();
        else cp_wait0();
        __syncthreads();
        if (t + 3 < NKT) { load_tile(sb, t + 3, (t + 3) & 3, bm, bn, tid); cp_commit(); }

        uint32_t sA = sb + (t & 3) * STAGE_BYTES;
        uint32_t sB = sA + TILE_M * 128;
        #pragma unroll
        for (int ks = 0; ks < 4; ++ks) {
            uint32_t afr[4][4];
            #pragma unroll
            for (int mi = 0; mi < 4; ++mi) {
                int r = rowA + mi * 16;
                int j = ks * 2 + kgrpA;
                ldsm4(afr[mi], sA + r * 128 + ((j ^ (r & 7)) << 4));
            }
            uint32_t bfr[4][4];
            #pragma unroll
            for (int nip = 0; nip < 4; ++nip) {
                int n = nBrow + nip * 16;
                int j = ks * 2 + kgrpB;
                ldsm4(bfr[nip], sB + n * 128 + ((j ^ (n & 7)) << 4));
            }
            #pragma unroll
            for (int mi = 0; mi < 4; ++mi)
                #pragma unroll
                for (int ni = 0; ni < 8; ++ni)
                    mma16816(acc[mi][ni], afr[mi], &bfr[ni >> 1][(ni & 1) * 2]);
        }
    }

    // ---------------- epilogue ----------------
    int seg = bn >> 2;                          // planar segment (0:u0, 1:g1, 2:g2)
    int nlocbase = (bn & 3) * 256 + warp_n;
    int g = lane >> 2, tq = lane & 3;
    #pragma unroll
    for (int mi = 0; mi < 4; ++mi) {
        int r0 = bm * TILE_M + warp_m + mi * 16 + g;
        #pragma unroll
        for (int ni = 0; ni < 8; ++ni) {
            int c = nlocbase + ni * 8 + 2 * tq;
            if (seg == 0) {
                *(__half2*)(g_u0h + (size_t)r0 * D_DIM + c) =
                    __floats2half2_rn(acc[mi][ni][0], acc[mi][ni][1]);
                *(__half2*)(g_u0h + (size_t)(r0 + 8) * D_DIM + c) =
                    __floats2half2_rn(acc[mi][ni][2], acc[mi][ni][3]);
            } else {
                const float* bp = bias + (seg - 1) * D_DIM + c;
                float b0 = bp[0], b1 = bp[1];
                __half* outh = (seg == 1) ? g_g1 : g_g2;
                float s0 = 1.0f / (1.0f + __expf(-(acc[mi][ni][0] + b0)));
                float s1 = 1.0f / (1.0f + __expf(-(acc[mi][ni][1] + b1)));
                float s2 = 1.0f / (1.0f + __expf(-(acc[mi][ni][2] + b0)));
                float s3 = 1.0f / (1.0f + __expf(-(acc[mi][ni][3] + b1)));
                *(__half2*)(outh + (size_t)r0 * D_DIM + c) = __floats2half2_rn(s0, s1);
                *(__half2*)(outh + (size_t)(r0 + 8) * D_DIM + c) = __floats2half2_rn(s2, s3);
            }
        }
    }
}

// ---------------- scan (chunked linear recurrence), 2 lanes/thread ----------------
__global__ void __launch_bounds__(256) scan_pass1() {
    int p = (blockIdx.x * 256 + threadIdx.x) * 2;
    int ch = blockIdx.y;
    size_t base = (size_t)(ch * LC) * P_DIM + p;
    float Ax = 1.0f, Ay = 1.0f, Bx = 0.0f, By = 0.0f;
    #pragma unroll 4
    for (int t = 0; t < LC; ++t) {
        size_t o = base + (size_t)t * P_DIM;
        float2 u0 = __half22float2(*(const __half2*)(g_u0h + o));
        float2 g1 = __half22float2(*(const __half2*)(g_g1 + o));
        Ax *= g1.x; Ay *= g1.y;
        Bx = Bx * g1.x + u0.x * (1.0f - g1.x);
        By = By * g1.y + u0.y * (1.0f - g1.y);
    }
    size_t co = (size_t)ch * P_DIM + p;
    *(float2*)(g_cA + co) = make_float2(Ax, Ay);
    *(float2*)(g_cB + co) = make_float2(Bx, By);
}

__global__ void __launch_bounds__(256) scan_combine(const float* __restrict__ c0) {
    int p = (blockIdx.x * 256 + threadIdx.x) * 2;
    float2 c = *(const float2*)(c0 + p);
    #pragma unroll
    for (int ch = 0; ch < NC; ++ch) {
        size_t o = (size_t)ch * P_DIM + p;
        *(float2*)(g_cS + o) = c;
        float2 A = *(const float2*)(g_cA + o);
        float2 B = *(const float2*)(g_cB + o);
        c.x = A.x * c.x + B.x;
        c.y = A.y * c.y + B.y;
    }
}

__global__ void __launch_bounds__(256) scan_apply(const float* __restrict__ x,
                                                  float* __restrict__ h) {
    int p = (blockIdx.x * 256 + threadIdx.x) * 2;
    int ch = blockIdx.y;
    float2 c = *(const float2*)(g_cS + (size_t)ch * P_DIM + p);
    size_t base = (size_t)(ch * LC) * P_DIM + p;
    #pragma unroll 4
    for (int t = 0; t < LC; ++t) {
        size_t o = base + (size_t)t * P_DIM;
        float2 u0 = __half22float2(*(const __half2*)(g_u0h + o));
        float2 g1 = __half22float2(*(const __half2*)(g_g1 + o));
        float2 g2 = __half22float2(*(const __half2*)(g_g2 + o));
        float2 xv = *(const float2*)(x + o);
        c.x = (c.x - u0.x) * g1.x + u0.x;
        c.y = (c.y - u0.y) * g1.y + u0.y;
        float2 hv;
        hv.x = (tanhf(c.x) - xv.x) * g2.x + xv.x;
        hv.y = (tanhf(c.y) - xv.y) * g2.y + xv.y;
        *(float2*)(h + o) = hv;
    }
}

// ---------------- launch ----------------
extern "C" void kernel_launch(void* const* d_in, const int* in_sizes, int n_in,
                              void* d_out, int out_size) {
    const float* x    = (const float*)d_in[0];
    const float* W    = (const float*)d_in[1];
    const float* bias = (const float*)d_in[2];
    const float* c0   = (const float*)d_in[3];
    float* h = (float*)d_out;

    cudaFuncSetAttribute(gemm_kernel, cudaFuncAttributeMaxDynamicSharedMemorySize, SMEM_BYTES);

    conv_x_kernel<<<(M_DIM * D_DIM / 4) / 256, 256>>>(x);
    conv_w_kernel<<<(N_DIM * D_DIM) / 256, 256>>>(W);
    gemm_kernel<<<dim3(N_DIM / TILE_N, M_DIM / TILE_M), 256, SMEM_BYTES>>>(bias);
    scan_pass1<<<dim3(P_DIM / 512, NC), 256>>>();
    scan_combine<<<P_DIM / 512, 256>>>(c0);
    scan_apply<<<dim3(P_DIM / 512, NC), 256>>>(x, h);
}

// round 6
// speedup vs baseline: 1.0010x; 1.0010x over previous
#include <cuda_runtime.h>
#include <cuda_fp16.h>
#include <cstdint>
#include <cstddef>

// Problem dims
#define L_DIM 1024
#define B_DIM 32
#define D_DIM 1024
#define M_DIM (L_DIM * B_DIM)     // 32768 rows (l*B+b)
#define N_DIM 3072                // 3*D output cols (planar-permuted)
#define KA    1024                // A storage: x fp16
#define NKT   16                  // K = 1024 = 16 tiles of 64
#define P_DIM (B_DIM * D_DIM)     // 32768 lanes
#define NC    16                  // scan chunks
#define LC    64                  // steps per chunk

// ---------------- device scratch (static: no allocs allowed) ----------------
__device__ __half g_A[(size_t)M_DIM * KA];            // 64 MB: x fp16, (M, 1024)
__device__ __half g_Bm[(size_t)N_DIM * D_DIM];        // 6 MB: permuted W^T fp16
__device__ __half g_u0h[(size_t)M_DIM * D_DIM];       // 64 MB (fp16 u0)
__device__ __half g_g1[(size_t)M_DIM * D_DIM];        // 64 MB (post-sigmoid fp16)
__device__ __half g_g2[(size_t)M_DIM * D_DIM];        // 64 MB (post-sigmoid fp16)
__device__ float  g_cA[(size_t)NC * P_DIM];           // chunk A
__device__ float  g_cB[(size_t)NC * P_DIM];           // chunk B
__device__ float  g_cS[(size_t)NC * P_DIM];           // chunk start c

// ---------------- ptx helpers ----------------
__device__ __forceinline__ uint32_t smem_u32(const void* p) {
    uint32_t a;
    asm("{ .reg .u64 t; cvta.to.shared.u64 t, %1; cvt.u32.u64 %0, t; }" : "=r"(a) : "l"(p));
    return a;
}
__device__ __forceinline__ void cp16(uint32_t dst, const void* src) {
    asm volatile("cp.async.cg.shared.global [%0], [%1], 16;" :: "r"(dst), "l"(src));
}
__device__ __forceinline__ void cp_commit() { asm volatile("cp.async.commit_group;"); }
__device__ __forceinline__ void cp_wait2()  { asm volatile("cp.async.wait_group 2;"); }
__device__ __forceinline__ void cp_wait1()  { asm volatile("cp.async.wait_group 1;"); }
__device__ __forceinline__ void cp_wait0()  { asm volatile("cp.async.wait_group 0;"); }

__device__ __forceinline__ void ldsm4(uint32_t* r, uint32_t addr) {
    asm volatile("ldmatrix.sync.aligned.m8n8.x4.shared.b16 {%0,%1,%2,%3}, [%4];"
                 : "=r"(r[0]), "=r"(r[1]), "=r"(r[2]), "=r"(r[3]) : "r"(addr));
}
__device__ __forceinline__ void mma16816(float* d, const uint32_t* a, const uint32_t* b) {
    asm volatile(
        "mma.sync.aligned.m16n8k16.row.col.f32.f16.f16.f32 "
        "{%0,%1,%2,%3}, {%4,%5,%6,%7}, {%8,%9}, {%0,%1,%2,%3};"
        : "+f"(d[0]), "+f"(d[1]), "+f"(d[2]), "+f"(d[3])
        : "r"(a[0]), "r"(a[1]), "r"(a[2]), "r"(a[3]), "r"(b[0]), "r"(b[1]));
}

// ---------------- conversion kernels ----------------
__global__ void conv_x_kernel(const float* __restrict__ x) {
    int idx = blockIdx.x * blockDim.x + threadIdx.x;
    float4 v = *(const float4*)(x + (size_t)idx * 4);
    *(__half2*)(g_A + (size_t)idx * 4)     = __floats2half2_rn(v.x, v.y);
    *(__half2*)(g_A + (size_t)idx * 4 + 2) = __floats2half2_rn(v.z, v.w);
}

// W (D, 3D) interleaved -> planar-permuted transposed fp16: g_Bm[n][k]
// n in [0,3072): seg = n/1024, d = n%1024; src col = 3*d + seg
__global__ void conv_w_kernel(const float* __restrict__ W) {
    int idx = blockIdx.x * blockDim.x + threadIdx.x;      // < 3072*1024
    int n = idx >> 10, k = idx & 1023;
    int seg = n >> 10, d = n & 1023;
    g_Bm[(size_t)n * D_DIM + k] = __float2half_rn(W[(size_t)k * N_DIM + 3 * d + seg]);
}

// ---------------- GEMM: 128(M) x 256(N), 256 threads, warp tile 64x64, 4 stages ----------------
#define TILE_M 128
#define TILE_N 256
#define STAGE_BYTES (TILE_M * 128 + TILE_N * 128)   // 48KB
#define NSTAGE 4
#define SMEM_BYTES  (NSTAGE * STAGE_BYTES)          // 192KB

__device__ __forceinline__ void load_tile(uint32_t sb, int t, int stage, int bm, int bn, int tid) {
    int koff = t * 64;
    uint32_t sA = sb + stage * STAGE_BYTES;
    uint32_t sB = sA + TILE_M * 128;
    const __half* Ag = g_A  + (size_t)(bm * TILE_M) * KA + koff;
    const __half* Bg = g_Bm + (size_t)(bn * TILE_N) * D_DIM + koff;
    #pragma unroll
    for (int it = 0; it < 12; ++it) {
        int i = tid + it * 256;                  // 0..3071
        if (i < 1024) {
            int row = i >> 3, j = i & 7;
            cp16(sA + row * 128 + ((j ^ (row & 7)) << 4),
                 Ag + (size_t)row * KA + j * 8);
        } else {
            int li = i - 1024;
            int row = li >> 3, j = li & 7;
            cp16(sB + row * 128 + ((j ^ (row & 7)) << 4),
                 Bg + (size_t)row * D_DIM + j * 8);
        }
    }
}

__global__ void __launch_bounds__(256, 1)
gemm_kernel(const float* __restrict__ bias) {
    extern __shared__ __align__(1024) char smem[];
    uint32_t sb = smem_u32(smem);
    int tid = threadIdx.x, wid = tid >> 5, lane = tid & 31;
    int bn = blockIdx.x, bm = blockIdx.y;
    int warp_m = (wid >> 2) * 64;     // 0,64
    int warp_n = (wid & 3) * 64;      // 0,64,128,192

    float acc[4][8][4];
    #pragma unroll
    for (int mi = 0; mi < 4; ++mi)
        #pragma unroll
        for (int ni = 0; ni < 8; ++ni)
            #pragma unroll
            for (int j = 0; j < 4; ++j) acc[mi][ni][j] = 0.0f;

    int rowA = warp_m + (lane & 15);
    int kgrpA = lane >> 4;
    int nBrow = warp_n + ((lane >> 4) << 3) + (lane & 7);
    int kgrpB = (lane >> 3) & 1;

    load_tile(sb, 0, 0, bm, bn, tid); cp_commit();
    load_tile(sb, 1, 1, bm, bn, tid); cp_commit();
    load_tile(sb, 2, 2, bm, bn, tid); cp_commit();

    for (int t = 0; t < NKT; ++t) {
        if (t < NKT - 2) cp_wait2();
        else if (t == NKT - 2) cp_wait1();
        else cp_wait0();
        __syncthreads();
        if (t + 3 < NKT) { load_tile(sb, t + 3, (t + 3) & 3, bm, bn, tid); cp_commit(); }

        uint32_t sA = sb + (t & 3) * STAGE_BYTES;
        uint32_t sB = sA + TILE_M * 128;
        #pragma unroll
        for (int ks = 0; ks < 4; ++ks) {
            uint32_t afr[4][4];
            #pragma unroll
            for (int mi = 0; mi < 4; ++mi) {
                int r = rowA + mi * 16;
                int j = ks * 2 + kgrpA;
                ldsm4(afr[mi], sA + r * 128 + ((j ^ (r & 7)) << 4));
            }
            uint32_t bfr[4][4];
            #pragma unroll
            for (int nip = 0; nip < 4; ++nip) {
                int n = nBrow + nip * 16;
                int j = ks * 2 + kgrpB;
                ldsm4(bfr[nip], sB + n * 128 + ((j ^ (n & 7)) << 4));
            }
            #pragma unroll
            for (int mi = 0; mi < 4; ++mi)
                #pragma unroll
                for (int ni = 0; ni < 8; ++ni)
                    mma16816(acc[mi][ni], afr[mi], &bfr[ni >> 1][(ni & 1) * 2]);
        }
    }

    // ---------------- epilogue ----------------
    int seg = bn >> 2;                          // planar segment (0:u0, 1:g1, 2:g2)
    int nlocbase = (bn & 3) * 256 + warp_n;
    int g = lane >> 2, tq = lane & 3;
    #pragma unroll
    for (int mi = 0; mi < 4; ++mi) {
        int r0 = bm * TILE_M + warp_m + mi * 16 + g;
        #pragma unroll
        for (int ni = 0; ni < 8; ++ni) {
            int c = nlocbase + ni * 8 + 2 * tq;
            if (seg == 0) {
                *(__half2*)(g_u0h + (size_t)r0 * D_DIM + c) =
                    __floats2half2_rn(acc[mi][ni][0], acc[mi][ni][1]);
                *(__half2*)(g_u0h + (size_t)(r0 + 8) * D_DIM + c) =
                    __floats2half2_rn(acc[mi][ni][2], acc[mi][ni][3]);
            } else {
                const float* bp = bias + (seg - 1) * D_DIM + c;
                float b0 = bp[0], b1 = bp[1];
                __half* outh = (seg == 1) ? g_g1 : g_g2;
                float s0 = 1.0f / (1.0f + __expf(-(acc[mi][ni][0] + b0)));
                float s1 = 1.0f / (1.0f + __expf(-(acc[mi][ni][1] + b1)));
                float s2 = 1.0f / (1.0f + __expf(-(acc[mi][ni][2] + b0)));
                float s3 = 1.0f / (1.0f + __expf(-(acc[mi][ni][3] + b1)));
                *(__half2*)(outh + (size_t)r0 * D_DIM + c) = __floats2half2_rn(s0, s1);
                *(__half2*)(outh + (size_t)(r0 + 8) * D_DIM + c) = __floats2half2_rn(s2, s3);
            }
        }
    }
}

// ---------------- scan (chunked linear recurrence), 2 lanes/thread ----------------
__global__ void __launch_bounds__(256) scan_pass1() {
    int p = (blockIdx.x * 256 + threadIdx.x) * 2;
    int ch = blockIdx.y;
    size_t base = (size_t)(ch * LC) * P_DIM + p;
    float Ax = 1.0f, Ay = 1.0f, Bx = 0.0f, By = 0.0f;
    #pragma unroll 4
    for (int t = 0; t < LC; ++t) {
        size_t o = base + (size_t)t * P_DIM;
        float2 u0 = __half22float2(*(const __half2*)(g_u0h + o));
        float2 g1 = __half22float2(*(const __half2*)(g_g1 + o));
        Ax *= g1.x; Ay *= g1.y;
        Bx = Bx * g1.x + u0.x * (1.0f - g1.x);
        By = By * g1.y + u0.y * (1.0f - g1.y);
    }
    size_t co = (size_t)ch * P_DIM + p;
    *(float2*)(g_cA + co) = make_float2(Ax, Ay);
    *(float2*)(g_cB + co) = make_float2(Bx, By);
}

__global__ void __launch_bounds__(256) scan_combine(const float* __restrict__ c0) {
    int p = (blockIdx.x * 256 + threadIdx.x) * 2;
    float2 c = *(const float2*)(c0 + p);
    #pragma unroll
    for (int ch = 0; ch < NC; ++ch) {
        size_t o = (size_t)ch * P_DIM + p;
        *(float2*)(g_cS + o) = c;
        float2 A = *(const float2*)(g_cA + o);
        float2 B = *(const float2*)(g_cB + o);
        c.x = A.x * c.x + B.x;
        c.y = A.y * c.y + B.y;
    }
}

__global__ void __launch_bounds__(256) scan_apply(const float* __restrict__ x,
                                                  float* __restrict__ h) {
    int p = (blockIdx.x * 256 + threadIdx.x) * 2;
    int ch = blockIdx.y;
    float2 c = *(const float2*)(g_cS + (size_t)ch * P_DIM + p);
    size_t base = (size_t)(ch * LC) * P_DIM + p;
    #pragma unroll 4
    for (int t = 0; t < LC; ++t) {
        size_t o = base + (size_t)t * P_DIM;
        float2 u0 = __half22float2(*(const __half2*)(g_u0h + o));
        float2 g1 = __half22float2(*(const __half2*)(g_g1 + o));
        float2 g2 = __half22float2(*(const __half2*)(g_g2 + o));
        float2 xv = *(const float2*)(x + o);
        c.x = (c.x - u0.x) * g1.x + u0.x;
        c.y = (c.y - u0.y) * g1.y + u0.y;
        float2 hv;
        hv.x = (tanhf(c.x) - xv.x) * g2.x + xv.x;
        hv.y = (tanhf(c.y) - xv.y) * g2.y + xv.y;
        *(float2*)(h + o) = hv;
    }
}

// ---------------- launch ----------------
extern "C" void kernel_launch(void* const* d_in, const int* in_sizes, int n_in,
                              void* d_out, int out_size) {
    const float* x    = (const float*)d_in[0];
    const float* W    = (const float*)d_in[1];
    const float* bias = (const float*)d_in[2];
    const float* c0   = (const float*)d_in[3];
    float* h = (float*)d_out;

    static int attr_done = 0;
    if (!attr_done) {
        cudaFuncSetAttribute(gemm_kernel, cudaFuncAttributeMaxDynamicSharedMemorySize, SMEM_BYTES);
        attr_done = 1;
    }

    conv_x_kernel<<<(M_DIM * D_DIM / 4) / 256, 256>>>(x);
    conv_w_kernel<<<(N_DIM * D_DIM) / 256, 256>>>(W);
    gemm_kernel<<<dim3(N_DIM / TILE_N, M_DIM / TILE_M), 256, SMEM_BYTES>>>(bias);
    scan_pass1<<<dim3(P_DIM / 512, NC), 256>>>();
    scan_combine<<<P_DIM / 512, 256>>>(c0);
    scan_apply<<<dim3(P_DIM / 512, NC), 256>>>(x, h);
}

// round 9
// speedup vs baseline: 1.2043x; 1.2030x over previous
#include <cuda_runtime.h>
#include <cuda_fp16.h>
#include <cstdint>
#include <cstddef>

// Problem dims
#define L_DIM 1024
#define B_DIM 32
#define D_DIM 1024
#define M_DIM (L_DIM * B_DIM)     // 32768 rows (l*B+b)
#define N_DIM 3072                // 3*D output cols (planar-permuted)
#define KA    1024                // A storage: x fp16
#define NKT   16                  // K = 1024 = 16 tiles of 64
#define P_DIM (B_DIM * D_DIM)     // 32768 lanes
#define NC    16                  // scan chunks
#define LC    64                  // steps per chunk

// ---------------- device scratch (static: no allocs allowed) ----------------
__device__ __half g_A[(size_t)M_DIM * KA];            // 64 MB: x fp16, (M, 1024)
__device__ __half g_Bm[(size_t)N_DIM * D_DIM];        // 6 MB: permuted W^T fp16
__device__ __half g_u0h[(size_t)M_DIM * D_DIM];       // 64 MB (fp16 u0)
__device__ __half g_g1[(size_t)M_DIM * D_DIM];        // 64 MB (post-sigmoid fp16)
__device__ __half g_g2[(size_t)M_DIM * D_DIM];        // 64 MB (post-sigmoid fp16)
__device__ float  g_cA[(size_t)NC * P_DIM];           // chunk A
__device__ float  g_cB[(size_t)NC * P_DIM];           // chunk B
__device__ float  g_cS[(size_t)NC * P_DIM];           // chunk start c

// ---------------- ptx helpers ----------------
__device__ __forceinline__ uint32_t smem_u32(const void* p) {
    uint32_t a;
    asm("{ .reg .u64 t; cvta.to.shared.u64 t, %1; cvt.u32.u64 %0, t; }" : "=r"(a) : "l"(p));
    return a;
}
__device__ __forceinline__ void cp16(uint32_t dst, const void* src) {
    asm volatile("cp.async.cg.shared.global [%0], [%1], 16;" :: "r"(dst), "l"(src));
}
__device__ __forceinline__ void cp_commit() { asm volatile("cp.async.commit_group;"); }
__device__ __forceinline__ void cp_wait1()  { asm volatile("cp.async.wait_group 1;"); }
__device__ __forceinline__ void cp_wait0()  { asm volatile("cp.async.wait_group 0;"); }

__device__ __forceinline__ void ldsm4(uint32_t* r, uint32_t addr) {
    asm volatile("ldmatrix.sync.aligned.m8n8.x4.shared.b16 {%0,%1,%2,%3}, [%4];"
                 : "=r"(r[0]), "=r"(r[1]), "=r"(r[2]), "=r"(r[3]) : "r"(addr));
}
__device__ __forceinline__ void mma16816(float* d, const uint32_t* a, const uint32_t* b) {
    asm volatile(
        "mma.sync.aligned.m16n8k16.row.col.f32.f16.f16.f32 "
        "{%0,%1,%2,%3}, {%4,%5,%6,%7}, {%8,%9}, {%0,%1,%2,%3};"
        : "+f"(d[0]), "+f"(d[1]), "+f"(d[2]), "+f"(d[3])
        : "r"(a[0]), "r"(a[1]), "r"(a[2]), "r"(a[3]), "r"(b[0]), "r"(b[1]));
}

// ---------------- conversion kernels ----------------
__global__ void conv_x_kernel(const float* __restrict__ x) {
    int idx = blockIdx.x * blockDim.x + threadIdx.x;
    float4 v = *(const float4*)(x + (size_t)idx * 4);
    *(__half2*)(g_A + (size_t)idx * 4)     = __floats2half2_rn(v.x, v.y);
    *(__half2*)(g_A + (size_t)idx * 4 + 2) = __floats2half2_rn(v.z, v.w);
}

// W (D, 3D) interleaved -> planar-permuted transposed fp16: g_Bm[n][k]
__global__ void conv_w_kernel(const float* __restrict__ W) {
    int idx = blockIdx.x * blockDim.x + threadIdx.x;      // < 3072*1024
    int n = idx >> 10, k = idx & 1023;
    int seg = n >> 10, d = n & 1023;
    g_Bm[(size_t)n * D_DIM + k] = __float2half_rn(W[(size_t)k * N_DIM + 3 * d + seg]);
}

// ---------------- GEMM: 128(M) x 128(N), 256 threads, 2 CTAs/SM, warp tile 32x64 ----------------
#define TILE_M 128
#define TILE_N 128
#define STAGE_BYTES (TILE_M * 128 + TILE_N * 128)   // 32KB
#define NSTAGE 3
#define SMEM_BYTES  (NSTAGE * STAGE_BYTES)          // 96KB -> 2 CTAs/SM

__device__ __forceinline__ void load_tile(uint32_t sb, int t, int stage, int bm, int bn, int tid) {
    int koff = t * 64;
    uint32_t sA = sb + stage * STAGE_BYTES;
    uint32_t sB = sA + TILE_M * 128;
    const __half* Ag = g_A  + (size_t)(bm * TILE_M) * KA + koff;
    const __half* Bg = g_Bm + (size_t)(bn * TILE_N) * D_DIM + koff;
    #pragma unroll
    for (int it = 0; it < 8; ++it) {
        int i = tid + it * 256;                  // 0..2047
        if (i < 1024) {
            int row = i >> 3, j = i & 7;
            cp16(sA + row * 128 + ((j ^ (row & 7)) << 4),
                 Ag + (size_t)row * KA + j * 8);
        } else {
            int li = i - 1024;
            int row = li >> 3, j = li & 7;
            cp16(sB + row * 128 + ((j ^ (row & 7)) << 4),
                 Bg + (size_t)row * D_DIM + j * 8);
        }
    }
}

__global__ void __launch_bounds__(256, 2)
gemm_kernel(const float* __restrict__ bias) {
    extern __shared__ __align__(1024) char smem[];
    uint32_t sb = smem_u32(smem);
    int tid = threadIdx.x, wid = tid >> 5, lane = tid & 31;
    int bn = blockIdx.x, bm = blockIdx.y;
    int warp_m = (wid >> 1) * 32;     // 0,32,64,96
    int warp_n = (wid & 1) * 64;      // 0,64

    float acc[2][8][4];
    #pragma unroll
    for (int mi = 0; mi < 2; ++mi)
        #pragma unroll
        for (int ni = 0; ni < 8; ++ni)
            #pragma unroll
            for (int j = 0; j < 4; ++j) acc[mi][ni][j] = 0.0f;

    int rowA = warp_m + (lane & 15);
    int kgrpA = lane >> 4;
    int nBrow = warp_n + ((lane >> 4) << 3) + (lane & 7);
    int kgrpB = (lane >> 3) & 1;

    load_tile(sb, 0, 0, bm, bn, tid); cp_commit();
    load_tile(sb, 1, 1, bm, bn, tid); cp_commit();

    for (int t = 0; t < NKT; ++t) {
        if (t < NKT - 1) cp_wait1(); else cp_wait0();
        __syncthreads();
        if (t + 2 < NKT) { load_tile(sb, t + 2, (t + 2) % 3, bm, bn, tid); cp_commit(); }

        uint32_t sA = sb + (t % 3) * STAGE_BYTES;
        uint32_t sB = sA + TILE_M * 128;
        #pragma unroll
        for (int ks = 0; ks < 4; ++ks) {
            uint32_t afr[2][4];
            #pragma unroll
            for (int mi = 0; mi < 2; ++mi) {
                int r = rowA + mi * 16;
                int j = ks * 2 + kgrpA;
                ldsm4(afr[mi], sA + r * 128 + ((j ^ (r & 7)) << 4));
            }
            uint32_t bfr[4][4];
            #pragma unroll
            for (int nip = 0; nip < 4; ++nip) {
                int n = nBrow + nip * 16;
                int j = ks * 2 + kgrpB;
                ldsm4(bfr[nip], sB + n * 128 + ((j ^ (n & 7)) << 4));
            }
            #pragma unroll
            for (int mi = 0; mi < 2; ++mi)
                #pragma unroll
                for (int ni = 0; ni < 8; ++ni)
                    mma16816(acc[mi][ni], afr[mi], &bfr[ni >> 1][(ni & 1) * 2]);
        }
    }

    // ---------------- epilogue ----------------
    int seg = bn >> 3;                          // 8 x 128-col tiles per planar segment
    int nlocbase = (bn & 7) * 128 + warp_n;
    int g = lane >> 2, tq = lane & 3;
    #pragma unroll
    for (int mi = 0; mi < 2; ++mi) {
        int r0 = bm * TILE_M + warp_m + mi * 16 + g;
        #pragma unroll
        for (int ni = 0; ni < 8; ++ni) {
            int c = nlocbase + ni * 8 + 2 * tq;
            if (seg == 0) {
                *(__half2*)(g_u0h + (size_t)r0 * D_DIM + c) =
                    __floats2half2_rn(acc[mi][ni][0], acc[mi][ni][1]);
                *(__half2*)(g_u0h + (size_t)(r0 + 8) * D_DIM + c) =
                    __floats2half2_rn(acc[mi][ni][2], acc[mi][ni][3]);
            } else {
                const float* bp = bias + (seg - 1) * D_DIM + c;
                float b0 = bp[0], b1 = bp[1];
                __half* outh = (seg == 1) ? g_g1 : g_g2;
                float s0 = 1.0f / (1.0f + __expf(-(acc[mi][ni][0] + b0)));
                float s1 = 1.0f / (1.0f + __expf(-(acc[mi][ni][1] + b1)));
                float s2 = 1.0f / (1.0f + __expf(-(acc[mi][ni][2] + b0)));
                float s3 = 1.0f / (1.0f + __expf(-(acc[mi][ni][3] + b1)));
                *(__half2*)(outh + (size_t)r0 * D_DIM + c) = __floats2half2_rn(s0, s1);
                *(__half2*)(outh + (size_t)(r0 + 8) * D_DIM + c) = __floats2half2_rn(s2, s3);
            }
        }
    }
}

// ---------------- scan (chunked linear recurrence), 2 lanes/thread ----------------
__global__ void __launch_bounds__(256) scan_pass1() {
    int p = (blockIdx.x * 256 + threadIdx.x) * 2;
    int ch = blockIdx.y;
    size_t base = (size_t)(ch * LC) * P_DIM + p;
    float Ax = 1.0f, Ay = 1.0f, Bx = 0.0f, By = 0.0f;
    #pragma unroll 4
    for (int t = 0; t < LC; ++t) {
        size_t o = base + (size_t)t * P_DIM;
        float2 u0 = __half22float2(*(const __half2*)(g_u0h + o));
        float2 g1 = __half22float2(*(const __half2*)(g_g1 + o));
        Ax *= g1.x; Ay *= g1.y;
        Bx = Bx * g1.x + u0.x * (1.0f - g1.x);
        By = By * g1.y + u0.y * (1.0f - g1.y);
    }
    size_t co = (size_t)ch * P_DIM + p;
    *(float2*)(g_cA + co) = make_float2(Ax, Ay);
    *(float2*)(g_cB + co) = make_float2(Bx, By);
}

__global__ void __launch_bounds__(256) scan_combine(const float* __restrict__ c0) {
    int p = (blockIdx.x * 256 + threadIdx.x) * 2;
    float2 c = *(const float2*)(c0 + p);
    #pragma unroll
    for (int ch = 0; ch < NC; ++ch) {
        size_t o = (size_t)ch * P_DIM + p;
        *(float2*)(g_cS + o) = c;
        float2 A = *(const float2*)(g_cA + o);
        float2 B = *(const float2*)(g_cB + o);
        c.x = A.x * c.x + B.x;
        c.y = A.y * c.y + B.y;
    }
}

__global__ void __launch_bounds__(256) scan_apply(const float* __restrict__ x,
                                                  float* __restrict__ h) {
    int p = (blockIdx.x * 256 + threadIdx.x) * 2;
    int ch = blockIdx.y;
    float2 c = *(const float2*)(g_cS + (size_t)ch * P_DIM + p);
    size_t base = (size_t)(ch * LC) * P_DIM + p;
    #pragma unroll 4
    for (int t = 0; t < LC; ++t) {
        size_t o = base + (size_t)t * P_DIM;
        float2 u0 = __half22float2(*(const __half2*)(g_u0h + o));
        float2 g1 = __half22float2(*(const __half2*)(g_g1 + o));
        float2 g2 = __half22float2(*(const __half2*)(g_g2 + o));
        float2 xv = *(const float2*)(x + o);
        c.x = (c.x - u0.x) * g1.x + u0.x;
        c.y = (c.y - u0.y) * g1.y + u0.y;
        float2 hv;
        hv.x = (tanhf(c.x) - xv.x) * g2.x + xv.x;
        hv.y = (tanhf(c.y) - xv.y) * g2.y + xv.y;
        *(float2*)(h + o) = hv;
    }
}

// ---------------- launch ----------------
extern "C" void kernel_launch(void* const* d_in, const int* in_sizes, int n_in,
                              void* d_out, int out_size) {
    const float* x    = (const float*)d_in[0];
    const float* W    = (const float*)d_in[1];
    const float* bias = (const float*)d_in[2];
    const float* c0   = (const float*)d_in[3];
    float* h = (float*)d_out;

    static int attr_done = 0;
    if (!attr_done) {
        cudaFuncSetAttribute(gemm_kernel, cudaFuncAttributeMaxDynamicSharedMemorySize, SMEM_BYTES);
        attr_done = 1;
    }

    conv_x_kernel<<<(M_DIM * D_DIM / 4) / 256, 256>>>(x);
    conv_w_kernel<<<(N_DIM * D_DIM) / 256, 256>>>(W);
    gemm_kernel<<<dim3(N_DIM / TILE_N, M_DIM / TILE_M), 256, SMEM_BYTES>>>(bias);
    scan_pass1<<<dim3(P_DIM / 512, NC), 256>>>();
    scan_combine<<<P_DIM / 512, 256>>>(c0);
    scan_apply<<<dim3(P_DIM / 512, NC), 256>>>(x, h);
}